// round 7
// baseline (speedup 1.0000x reference)
#include <cuda_runtime.h>
#include <math.h>

#define CC 256
#define TT 4096
#define BB 8
#define BC (BB*CC)
#define ALPHA 0.8187307530779818f
#define ONE_M_ALPHA 0.1812692469220182f
#define A8 0.20189651799465540f   /* ALPHA^8 = exp(-1.6) */

typedef unsigned long long ull;

__device__ int g_cnt[BB];          // zero-init; self-reset each launch

__device__ __forceinline__ ull pk2(float lo, float hi) {
    ull r; asm("mov.b64 %0, {%1, %2};" : "=l"(r) : "f"(lo), "f"(hi)); return r;
}
__device__ __forceinline__ void upk2(float& lo, float& hi, ull v) {
    asm("mov.b64 {%0, %1}, %2;" : "=f"(lo), "=f"(hi) : "l"(v));
}
__device__ __forceinline__ void fma2(ull& d, ull a, ull b) {
    asm("fma.rn.f32x2 %0, %1, %2, %0;" : "+l"(d) : "l"(a), "l"(b));
}

// ---------------- fully fused: coeffs -> conv -> LIF scan -> (last block per batch) tail ----------------
// out layout: [0,BC) pred, [BC,2BC) true_latency, [2BC,3BC) act.
__global__ void __launch_bounds__(512, 2) fused_kernel(
        const float* __restrict__ x,
        const float* __restrict__ w3, const float* __restrict__ b3,
        const float* __restrict__ w5, const float* __restrict__ b5,
        const float* __restrict__ w9, const float* __restrict__ b9,
        const float* __restrict__ wred, const float* __restrict__ bred,
        const float* __restrict__ lat_scale,
        const float* __restrict__ OG, const float* __restrict__ bias,
        const float* __restrict__ W1, const float* __restrict__ b1,
        const float* __restrict__ W2, const float* __restrict__ b2,
        float* __restrict__ out) {
    __shared__ float sE[28];           // [27] = bias accumulator
    __shared__ ull sE2[27];
    __shared__ float swa[16], swb[16];
    __shared__ int s_first, s_last;
    // tail scratch (used only by 8 deciding blocks)
    __shared__ float4 sact4[64];
    __shared__ float smix[256];
    __shared__ float sh[128];
    __shared__ float sp[2048];

    int tid  = threadIdx.x;
    int lane = tid & 31;
    int wrp  = tid >> 5;
    int bc = blockIdx.x;
    int b  = bc >> 8;
    int c  = bc & 255;

    // ---- in-block effective-filter coefficients ----
    if (tid < 28) sE[tid] = 0.f;
    if (tid == 28) s_first = TT;
    __syncthreads();
    if (tid < 18) {
        int k = tid;
        int j = 18 * c + k;
        int bkt = j / 1536;
        int pc  = j - 1536 * bkt;
        const float* w  = (bkt == 0) ? w3 : (bkt == 1) ? w5 : w9;
        const float* bb = (bkt == 0) ? b3 : (bkt == 1) ? b5 : b9;
        int K   = (bkt == 0) ? 3 : (bkt == 1) ? 5 : 9;
        int pad = (K - 1) >> 1;
        int m = k / 6;
        float wr = wred[j];
        atomicAdd(&sE[27], wr * bb[pc]);
        for (int u = 0; u < K; u++)
            atomicAdd(&sE[m * 9 + 4 + u - pad], wr * w[pc * K + u]);
    }
    if (tid == 18) atomicAdd(&sE[27], bred[c]);
    __syncthreads();
    if (tid < 27) { float e = sE[tid] * ONE_M_ALPHA; sE2[tid] = pk2(e, e); }
    __syncthreads();
    float be = sE[27] * ONE_M_ALPHA;

    // ---- conv: 8 timesteps/thread, halos by direct (L1-hit) LDG ----
    ull U[4];
    ull be2 = pk2(be, be);
    #pragma unroll
    for (int p = 0; p < 4; p++) U[p] = be2;

    const float4 z4 = make_float4(0.f, 0.f, 0.f, 0.f);
    #pragma unroll
    for (int m = 0; m < 3; m++) {
        int xch = (3 * c + m) & 255;
        const float4* row4 = (const float4*)(x + ((size_t)(b * CC + xch)) * TT);
        float4 c0 = row4[tid * 2 + 0];
        float4 c1 = row4[tid * 2 + 1];
        float4 hp = (tid > 0)   ? row4[tid * 2 - 1] : z4;
        float4 hn = (tid < 511) ? row4[tid * 2 + 2] : z4;

        float w[16];
        w[0]=hp.x;  w[1]=hp.y;  w[2]=hp.z;  w[3]=hp.w;
        w[4]=c0.x;  w[5]=c0.y;  w[6]=c0.z;  w[7]=c0.w;
        w[8]=c1.x;  w[9]=c1.y;  w[10]=c1.z; w[11]=c1.w;
        w[12]=hn.x; w[13]=hn.y; w[14]=hn.z; w[15]=hn.w;

        ull p0[8], p1[7];
        #pragma unroll
        for (int k = 0; k < 8; k++) p0[k] = pk2(w[2*k], w[2*k+1]);
        #pragma unroll
        for (int k = 0; k < 7; k++) p1[k] = pk2(w[2*k+1], w[2*k+2]);

        #pragma unroll
        for (int t = 0; t < 9; t++) {
            ull e2 = sE2[m * 9 + t];
            if ((t & 1) == 0) {
                #pragma unroll
                for (int p = 0; p < 4; p++) fma2(U[p], e2, p0[p + (t >> 1)]);
            } else {
                #pragma unroll
                for (int p = 0; p < 4; p++) fma2(U[p], e2, p1[p + (t >> 1)]);
            }
        }
    }

    float u[8];
    #pragma unroll
    for (int p = 0; p < 4; p++) upk2(u[2*p], u[2*p+1], U[p]);

    // ---- segment transform V -> A8*V + bacc; two-level scan ----
    float bacc = 0.f;
    #pragma unroll
    for (int jj = 0; jj < 8; jj++) bacc = fmaf(ALPHA, bacc, u[jj]);

    float a = A8, bs = bacc;
    #pragma unroll
    for (int s = 1; s < 32; s <<= 1) {
        float ao = __shfl_up_sync(0xffffffffu, a, s);
        float bo = __shfl_up_sync(0xffffffffu, bs, s);
        if (lane >= s) { bs = fmaf(a, bo, bs); a *= ao; }
    }
    if (lane == 31) { swa[wrp] = a; swb[wrp] = bs; }
    __syncthreads();

    float pb = 0.f;
    for (int ww = 0; ww < wrp; ww++) pb = fmaf(swa[ww], pb, swb[ww]);

    float ae  = __shfl_up_sync(0xffffffffu, a, 1);
    float bse = __shfl_up_sync(0xffffffffu, bs, 1);
    if (lane == 0) { ae = 1.f; bse = 0.f; }
    float V = fmaf(ae, pb, bse);

    int t0 = tid * 8;
    int ft = 0x7fffffff;
    #pragma unroll
    for (int jj = 0; jj < 8; jj++) {
        V = fmaf(ALPHA, V, u[jj]);
        if (V >= 1.0f && ft == 0x7fffffff) ft = t0 + jj;
    }
    if (ft != 0x7fffffff) atomicMin(&s_first, ft);
    __syncthreads();

    if (tid == 0) {
        float tl = (float)s_first;
        out[BC + bc] = tl;
        float scale = fmaxf(lat_scale[0], 0.001f);
        out[2 * BC + bc] = expf(-tl / scale);
        __threadfence();
        int prev = atomicAdd(&g_cnt[b], 1);
        s_last = (prev == CC - 1) ? 1 : 0;
    }
    __syncthreads();
    if (!s_last) return;

    // ================= tail (one block per batch, the last arriver) =================
    int t = tid;
    if (t < 64) sact4[t] = ((const float4*)(out + 2 * BC + b * CC))[t];
    __syncthreads();

    // mix: 16 warps x 16 outputs
    const float4* OG4 = (const float4*)OG;
    #pragma unroll 4
    for (int oo = 0; oo < 16; oo++) {
        int i = wrp * 16 + oo;
        float4 g0 = OG4[i * 64 + lane];
        float4 g1 = OG4[i * 64 + 32 + lane];
        float4 a0 = sact4[lane];
        float4 a1 = sact4[32 + lane];
        float acc = g0.x * a0.x;
        acc = fmaf(g0.y, a0.y, acc);
        acc = fmaf(g0.z, a0.z, acc);
        acc = fmaf(g0.w, a0.w, acc);
        acc = fmaf(g1.x, a1.x, acc);
        acc = fmaf(g1.y, a1.y, acc);
        acc = fmaf(g1.z, a1.z, acc);
        acc = fmaf(g1.w, a1.w, acc);
        #pragma unroll
        for (int s = 16; s > 0; s >>= 1) acc += __shfl_xor_sync(0xffffffffu, acc, s);
        if (lane == 0) smix[i] = acc + bias[i];
    }
    __syncthreads();

    // h: 128 outputs via float4; 16 j-chunks of 16
    {
        const float4* W14 = (const float4*)W1;
        int il = t & 31;
        int ch = t >> 5;
        float4 acc = make_float4(0.f, 0.f, 0.f, 0.f);
        #pragma unroll 8
        for (int jj = 0; jj < 16; jj++) {
            int j = ch * 16 + jj;
            float mj = smix[j];
            float4 wr = W14[j * 32 + il];
            acc.x = fmaf(mj, wr.x, acc.x);
            acc.y = fmaf(mj, wr.y, acc.y);
            acc.z = fmaf(mj, wr.z, acc.z);
            acc.w = fmaf(mj, wr.w, acc.w);
        }
        ((float4*)sp)[ch * 32 + il] = acc;
    }
    __syncthreads();
    if (t < 128) {
        float s = b1[t];
        #pragma unroll
        for (int ch = 0; ch < 16; ch++) s += sp[ch * 128 + t];
        sh[t] = fmaxf(s, 0.f);
    }
    __syncthreads();

    // pred: 256 outputs via float4; 8 k-chunks of 16
    {
        const float4* W24 = (const float4*)W2;
        int il = t & 63;
        int ch = t >> 6;
        float4 acc = make_float4(0.f, 0.f, 0.f, 0.f);
        #pragma unroll 8
        for (int kk = 0; kk < 16; kk++) {
            int k = ch * 16 + kk;
            float hk = sh[k];
            float4 wr = W24[k * 64 + il];
            acc.x = fmaf(hk, wr.x, acc.x);
            acc.y = fmaf(hk, wr.y, acc.y);
            acc.z = fmaf(hk, wr.z, acc.z);
            acc.w = fmaf(hk, wr.w, acc.w);
        }
        ((float4*)sp)[ch * 64 + il] = acc;
    }
    __syncthreads();
    if (t < 256) {
        float r = b2[t];
        #pragma unroll
        for (int ch = 0; ch < 8; ch++) r += sp[ch * 256 + t];
        float spv = (r > 20.f) ? r : log1pf(expf(r));
        out[b * CC + t] = fminf(spv, 4096.0f);
    }
    if (t == 0) g_cnt[b] = 0;      // reset for next (graph-replayed) launch
}

extern "C" void kernel_launch(void* const* d_in, const int* in_sizes, int n_in,
                              void* d_out, int out_size) {
    const float* x    = (const float*)d_in[0];
    const float* w3   = (const float*)d_in[1];
    const float* b3   = (const float*)d_in[2];
    const float* w5   = (const float*)d_in[3];
    const float* b5   = (const float*)d_in[4];
    const float* w9   = (const float*)d_in[5];
    const float* b9   = (const float*)d_in[6];
    const float* wred = (const float*)d_in[7];
    const float* bred = (const float*)d_in[8];
    const float* ls   = (const float*)d_in[9];
    const float* og   = (const float*)d_in[10];
    const float* bias = (const float*)d_in[11];
    const float* W1   = (const float*)d_in[12];
    const float* b1   = (const float*)d_in[13];
    const float* W2   = (const float*)d_in[14];
    const float* b2   = (const float*)d_in[15];
    float* out = (float*)d_out;

    fused_kernel<<<BC, 512>>>(x, w3, b3, w5, b5, w9, b9, wred, bred,
                              ls, og, bias, W1, b1, W2, b2, out);
}

// round 8
// speedup vs baseline: 1.4689x; 1.4689x over previous
#include <cuda_runtime.h>
#include <math.h>

#define CC 256
#define TT 4096
#define BB 8
#define BC (BB*CC)
#define ALPHA 0.8187307530779818f
#define ONE_M_ALPHA 0.1812692469220182f
#define A8 0.20189651799465540f   /* ALPHA^8 = exp(-1.6) */

typedef unsigned long long ull;

// Effective-filter coefficients, duplicated-pair packed: (e,e) as f32x2, already * (1-alpha)
__device__ ull   g_E2[CC][3][9];
__device__ float g_beP[CC][3];     // bias partials * (1-alpha); m=0 slot includes bred

__device__ __forceinline__ ull pk2(float lo, float hi) {
    ull r; asm("mov.b64 %0, {%1, %2};" : "=l"(r) : "f"(lo), "f"(hi)); return r;
}
__device__ __forceinline__ void upk2(float& lo, float& hi, ull v) {
    asm("mov.b64 {%0, %1}, %2;" : "=f"(lo), "=f"(hi) : "l"(v));
}
__device__ __forceinline__ void fma2(ull& d, ull a, ull b) {
    asm("fma.rn.f32x2 %0, %1, %2, %0;" : "+l"(d) : "l"(a), "l"(b));
}

// ---------------- prep: 8 lanes per (c,m) pair; shfl-tree reduction ----------------
__global__ void __launch_bounds__(256) prep_kernel(
        const float* __restrict__ w3, const float* __restrict__ b3,
        const float* __restrict__ w5, const float* __restrict__ b5,
        const float* __restrict__ w9, const float* __restrict__ b9,
        const float* __restrict__ wred, const float* __restrict__ bred) {
    int tid = blockIdx.x * 256 + threadIdx.x;
    int pg  = tid >> 3;            // 0..767
    int sub = tid & 7;
    if (pg >= 3 * CC) return;
    int c = pg / 3;
    int m = pg - 3 * c;
    int j0 = 18 * c + 6 * m;
    const float* w; const float* bb; int K, pc0;
    if (j0 < 6 * CC)       { w = w3; bb = b3; K = 3; pc0 = j0; }
    else if (j0 < 12 * CC) { w = w5; bb = b5; K = 5; pc0 = j0 - 6 * CC; }
    else                   { w = w9; bb = b9; K = 9; pc0 = j0 - 12 * CC; }
    int pad = (K - 1) / 2;

    float E[9];
    #pragma unroll
    for (int t = 0; t < 9; t++) E[t] = 0.f;
    float be = 0.f;

    if (sub < 6) {
        int r = sub;
        float wr = wred[c * 18 + 6 * m + r];
        be = wr * bb[pc0 + r];
        for (int u = 0; u < K; u++)
            E[4 + u - pad] = wr * w[(pc0 + r) * K + u];
    }
    #pragma unroll
    for (int s = 4; s > 0; s >>= 1) {
        #pragma unroll
        for (int t = 0; t < 9; t++) E[t] += __shfl_xor_sync(0xffffffffu, E[t], s);
        be += __shfl_xor_sync(0xffffffffu, be, s);
    }
    if (sub == 0) {
        #pragma unroll
        for (int t = 0; t < 9; t++) {
            float e = E[t] * ONE_M_ALPHA;
            g_E2[c][m][t] = pk2(e, e);
        }
        g_beP[c][m] = be * ONE_M_ALPHA + ((m == 0) ? bred[c] * ONE_M_ALPHA : 0.f);
    }
}

// ---------------- lif: one block per (b, c); 512 threads, 8 timesteps/thread ----------------
// Halos via direct predicated LDG.128 (L1/L2 hits) instead of shuffles.
// out layout: [0,BC) pred (by k_tail), [BC,2BC) true_latency, [2BC,3BC) act.
__global__ void __launch_bounds__(512, 2) lif_kernel(const float* __restrict__ x,
                                                     const float* __restrict__ lat_scale,
                                                     float* __restrict__ out) {
    __shared__ ull sE2[27];
    __shared__ float swa[16], swb[16];
    __shared__ float s_scale;
    __shared__ int s_first;

    int tid  = threadIdx.x;
    int lane = tid & 31;
    int wrp  = tid >> 5;
    int bc = blockIdx.x;
    int b  = bc >> 8;
    int c  = bc & 255;

    if (tid < 27) sE2[tid] = ((const ull*)g_E2)[c * 27 + tid];
    if (tid == 28) s_first = TT;
    if (tid == 29) s_scale = fmaxf(lat_scale[0], 0.001f);
    __syncthreads();

    float be = g_beP[c][0] + g_beP[c][1] + g_beP[c][2];

    ull U[4];
    ull be2 = pk2(be, be);
    #pragma unroll
    for (int p = 0; p < 4; p++) U[p] = be2;

    const float4 z4 = make_float4(0.f, 0.f, 0.f, 0.f);
    #pragma unroll
    for (int m = 0; m < 3; m++) {
        int xch = (3 * c + m) & 255;
        const float4* row4 = (const float4*)(x + ((size_t)(b * CC + xch)) * TT);
        // 4 independent loads: core [t0..t0+7] plus both halos
        float4 c0 = row4[tid * 2 + 0];
        float4 c1 = row4[tid * 2 + 1];
        float4 hp = (tid > 0)   ? row4[tid * 2 - 1] : z4;
        float4 hn = (tid < 511) ? row4[tid * 2 + 2] : z4;

        float w[16];
        w[0]=hp.x;  w[1]=hp.y;  w[2]=hp.z;  w[3]=hp.w;
        w[4]=c0.x;  w[5]=c0.y;  w[6]=c0.z;  w[7]=c0.w;
        w[8]=c1.x;  w[9]=c1.y;  w[10]=c1.z; w[11]=c1.w;
        w[12]=hn.x; w[13]=hn.y; w[14]=hn.z; w[15]=hn.w;

        ull p0[8], p1[7];
        #pragma unroll
        for (int k = 0; k < 8; k++) p0[k] = pk2(w[2*k], w[2*k+1]);
        #pragma unroll
        for (int k = 0; k < 7; k++) p1[k] = pk2(w[2*k+1], w[2*k+2]);

        #pragma unroll
        for (int t = 0; t < 9; t++) {
            ull e2 = sE2[m * 9 + t];
            if ((t & 1) == 0) {
                #pragma unroll
                for (int p = 0; p < 4; p++) fma2(U[p], e2, p0[p + (t >> 1)]);
            } else {
                #pragma unroll
                for (int p = 0; p < 4; p++) fma2(U[p], e2, p1[p + (t >> 1)]);
            }
        }
    }

    float u[8];
    #pragma unroll
    for (int p = 0; p < 4; p++) upk2(u[2*p], u[2*p+1], U[p]);

    // segment transform V -> A8*V + bacc
    float bacc = 0.f;
    #pragma unroll
    for (int jj = 0; jj < 8; jj++) bacc = fmaf(ALPHA, bacc, u[jj]);

    // warp-inclusive scan of (a,b) composition
    float a = A8, bs = bacc;
    #pragma unroll
    for (int s = 1; s < 32; s <<= 1) {
        float ao = __shfl_up_sync(0xffffffffu, a, s);
        float bo = __shfl_up_sync(0xffffffffu, bs, s);
        if (lane >= s) { bs = fmaf(a, bo, bs); a *= ao; }
    }
    if (lane == 31) { swa[wrp] = a; swb[wrp] = bs; }
    __syncthreads();

    float pb = 0.f;
    for (int ww = 0; ww < wrp; ww++) pb = fmaf(swa[ww], pb, swb[ww]);

    float ae  = __shfl_up_sync(0xffffffffu, a, 1);
    float bse = __shfl_up_sync(0xffffffffu, bs, 1);
    if (lane == 0) { ae = 1.f; bse = 0.f; }
    float V = fmaf(ae, pb, bse);   // V at start of this thread's segment

    int t0 = tid * 8;
    int ft = 0x7fffffff;
    #pragma unroll
    for (int jj = 0; jj < 8; jj++) {
        V = fmaf(ALPHA, V, u[jj]);
        if (V >= 1.0f && ft == 0x7fffffff) ft = t0 + jj;
    }
    if (ft != 0x7fffffff) atomicMin(&s_first, ft);
    __syncthreads();

    if (tid == 0) {
        float tl = (float)s_first;
        out[BC + bc] = tl;
        out[2 * BC + bc] = expf(-tl / s_scale);
    }
}

// ---------------- fused tail: act -> mix -> h -> pred. One block per batch row ----------------
__global__ void __launch_bounds__(256) k_tail(const float* __restrict__ OG,
                                              const float* __restrict__ bias,
                                              const float* __restrict__ W1,
                                              const float* __restrict__ b1,
                                              const float* __restrict__ W2,
                                              const float* __restrict__ b2,
                                              float* __restrict__ out) {
    __shared__ float4 sact4[64];
    __shared__ float smix[256];
    __shared__ float sh[128];
    __shared__ float sp[1024];

    int b = blockIdx.x;
    int t = threadIdx.x;
    int lane = t & 31;
    int wrp  = t >> 5;

    if (t < 64) sact4[t] = ((const float4*)(out + 2 * BC + b * CC))[t];
    __syncthreads();

    const float4* OG4 = (const float4*)OG;
    #pragma unroll 4
    for (int oo = 0; oo < 32; oo++) {
        int i = wrp * 32 + oo;
        float4 g0 = OG4[i * 64 + lane];
        float4 g1 = OG4[i * 64 + 32 + lane];
        float4 a0 = sact4[lane];
        float4 a1 = sact4[32 + lane];
        float acc = g0.x * a0.x;
        acc = fmaf(g0.y, a0.y, acc);
        acc = fmaf(g0.z, a0.z, acc);
        acc = fmaf(g0.w, a0.w, acc);
        acc = fmaf(g1.x, a1.x, acc);
        acc = fmaf(g1.y, a1.y, acc);
        acc = fmaf(g1.z, a1.z, acc);
        acc = fmaf(g1.w, a1.w, acc);
        #pragma unroll
        for (int s = 16; s > 0; s >>= 1) acc += __shfl_xor_sync(0xffffffffu, acc, s);
        if (lane == 0) smix[i] = acc + bias[i];
    }
    __syncthreads();

    {
        const float4* W14 = (const float4*)W1;
        int il = t & 31;
        int ch = t >> 5;
        float4 acc = make_float4(0.f, 0.f, 0.f, 0.f);
        #pragma unroll 8
        for (int jj = 0; jj < 32; jj++) {
            int j = ch * 32 + jj;
            float mj = smix[j];
            float4 wr = W14[j * 32 + il];
            acc.x = fmaf(mj, wr.x, acc.x);
            acc.y = fmaf(mj, wr.y, acc.y);
            acc.z = fmaf(mj, wr.z, acc.z);
            acc.w = fmaf(mj, wr.w, acc.w);
        }
        ((float4*)sp)[ch * 32 + il] = acc;
    }
    __syncthreads();
    if (t < 128) {
        float s = b1[t];
        #pragma unroll
        for (int ch = 0; ch < 8; ch++) s += sp[ch * 128 + t];
        sh[t] = fmaxf(s, 0.f);
    }
    __syncthreads();

    {
        const float4* W24 = (const float4*)W2;
        int il = t & 63;
        int ch = t >> 6;
        float4 acc = make_float4(0.f, 0.f, 0.f, 0.f);
        #pragma unroll 8
        for (int kk = 0; kk < 32; kk++) {
            int k = ch * 32 + kk;
            float hk = sh[k];
            float4 wr = W24[k * 64 + il];
            acc.x = fmaf(hk, wr.x, acc.x);
            acc.y = fmaf(hk, wr.y, acc.y);
            acc.z = fmaf(hk, wr.z, acc.z);
            acc.w = fmaf(hk, wr.w, acc.w);
        }
        ((float4*)sp)[ch * 64 + il] = acc;
    }
    __syncthreads();
    {
        float r = b2[t];
        #pragma unroll
        for (int ch = 0; ch < 4; ch++) r += sp[ch * 256 + t];
        float spv = (r > 20.f) ? r : log1pf(expf(r));
        out[b * CC + t] = fminf(spv, 4096.0f);
    }
}

extern "C" void kernel_launch(void* const* d_in, const int* in_sizes, int n_in,
                              void* d_out, int out_size) {
    const float* x    = (const float*)d_in[0];
    const float* w3   = (const float*)d_in[1];
    const float* b3   = (const float*)d_in[2];
    const float* w5   = (const float*)d_in[3];
    const float* b5   = (const float*)d_in[4];
    const float* w9   = (const float*)d_in[5];
    const float* b9   = (const float*)d_in[6];
    const float* wred = (const float*)d_in[7];
    const float* bred = (const float*)d_in[8];
    const float* ls   = (const float*)d_in[9];
    const float* og   = (const float*)d_in[10];
    const float* bias = (const float*)d_in[11];
    const float* W1   = (const float*)d_in[12];
    const float* b1   = (const float*)d_in[13];
    const float* W2   = (const float*)d_in[14];
    const float* b2   = (const float*)d_in[15];
    float* out = (float*)d_out;

    prep_kernel<<<24, 256>>>(w3, b3, w5, b5, w9, b9, wred, bred);
    lif_kernel<<<BC, 512>>>(x, ls, out);
    k_tail<<<BB, 256>>>(og, bias, W1, b1, W2, b2, out);
}

// round 9
// speedup vs baseline: 1.5411x; 1.0491x over previous
#include <cuda_runtime.h>
#include <math.h>

#define CC 256
#define TT 4096
#define BB 8
#define BC (BB*CC)
#define ALPHA 0.8187307530779818f
#define ONE_M_ALPHA 0.1812692469220182f
#define A8 0.20189651799465540f   /* ALPHA^8 = exp(-1.6) */

// Effective-filter coefficients (scalar), already * (1-alpha)
__device__ float g_E[CC][3][9];
__device__ float g_be[CC];         // combined bias * (1-alpha), includes bred

// ---------------- prep: 8 lanes per (c,m) pair; shfl-tree reduction ----------------
__global__ void __launch_bounds__(256) prep_kernel(
        const float* __restrict__ w3, const float* __restrict__ b3,
        const float* __restrict__ w5, const float* __restrict__ b5,
        const float* __restrict__ w9, const float* __restrict__ b9,
        const float* __restrict__ wred, const float* __restrict__ bred) {
    int tid = blockIdx.x * 256 + threadIdx.x;
    int pg  = tid >> 3;            // 0..767
    int sub = tid & 7;
    if (pg >= 3 * CC) return;
    int c = pg / 3;
    int m = pg - 3 * c;
    int j0 = 18 * c + 6 * m;
    const float* w; const float* bb; int K, pc0;
    if (j0 < 6 * CC)       { w = w3; bb = b3; K = 3; pc0 = j0; }
    else if (j0 < 12 * CC) { w = w5; bb = b5; K = 5; pc0 = j0 - 6 * CC; }
    else                   { w = w9; bb = b9; K = 9; pc0 = j0 - 12 * CC; }
    int pad = (K - 1) / 2;

    float E[9];
    #pragma unroll
    for (int t = 0; t < 9; t++) E[t] = 0.f;
    float be = 0.f;

    if (sub < 6) {
        int r = sub;
        float wr = wred[c * 18 + 6 * m + r];
        be = wr * bb[pc0 + r];
        for (int u = 0; u < K; u++)
            E[4 + u - pad] = wr * w[(pc0 + r) * K + u];
    }
    #pragma unroll
    for (int s = 4; s > 0; s >>= 1) {
        #pragma unroll
        for (int t = 0; t < 9; t++) E[t] += __shfl_xor_sync(0xffffffffu, E[t], s);
        be += __shfl_xor_sync(0xffffffffu, be, s);
    }
    if (sub == 0) {
        #pragma unroll
        for (int t = 0; t < 9; t++) g_E[c][m][t] = E[t] * ONE_M_ALPHA;
        // combine the 3 m-partials of the bias via global atomics-free: write partial, sum in lif?
        // simpler: atomicAdd into g_be (zeroed by m==0 writer trick is racy) -> use atomicAdd w/ reset below
    }
    // bias: accumulate all three partials with atomics after a deterministic zero:
    if (sub == 0 && m == 0) g_be[c] = (be + bred[c]) * ONE_M_ALPHA;
}

// second tiny pass folds m=1,2 bias partials (kept separate to stay deterministic)
__global__ void prep_bias2(const float* __restrict__ w3, const float* __restrict__ b3,
                           const float* __restrict__ w5, const float* __restrict__ b5,
                           const float* __restrict__ w9, const float* __restrict__ b9,
                           const float* __restrict__ wred, const float* __restrict__ bred) {
    int c = blockIdx.x * blockDim.x + threadIdx.x;
    if (c >= CC) return;
    float be = 0.f;
    #pragma unroll
    for (int m = 1; m < 3; m++) {
        int j0 = 18 * c + 6 * m;
        const float* bb; int pc0;
        if (j0 < 6 * CC)       { bb = b3; pc0 = j0; }
        else if (j0 < 12 * CC) { bb = b5; pc0 = j0 - 6 * CC; }
        else                   { bb = b9; pc0 = j0 - 12 * CC; }
        for (int r = 0; r < 6; r++)
            be += wred[c * 18 + 6 * m + r] * bb[pc0 + r];
    }
    g_be[c] += be * ONE_M_ALPHA;
}

// ---------------- lif: one block per (b, c); 512 threads, 8 timesteps/thread, SCALAR ----------------
// out layout: [0,BC) pred (by k_tail), [BC,2BC) true_latency, [2BC,3BC) act.
__global__ void __launch_bounds__(512, 3) lif_kernel(const float* __restrict__ x,
                                                     const float* __restrict__ lat_scale,
                                                     float* __restrict__ out) {
    __shared__ float sE[27];
    __shared__ float swa[16], swb[16];
    __shared__ float s_scale;
    __shared__ int s_first;

    int tid  = threadIdx.x;
    int lane = tid & 31;
    int wrp  = tid >> 5;
    int bc = blockIdx.x;
    int b  = bc >> 8;
    int c  = bc & 255;

    if (tid < 27) sE[tid] = ((const float*)g_E)[c * 27 + tid];
    if (tid == 28) s_first = TT;
    if (tid == 29) s_scale = fmaxf(lat_scale[0], 0.001f);
    __syncthreads();

    float u[8];
    float be = g_be[c];
    #pragma unroll
    for (int jj = 0; jj < 8; jj++) u[jj] = be;

    const float4 z4 = make_float4(0.f, 0.f, 0.f, 0.f);
    #pragma unroll
    for (int m = 0; m < 3; m++) {
        int xch = (3 * c + m) & 255;
        const float4* row4 = (const float4*)(x + ((size_t)(b * CC + xch)) * TT);
        float4 c0 = row4[tid * 2 + 0];
        float4 c1 = row4[tid * 2 + 1];
        float4 hp = (tid > 0)   ? row4[tid * 2 - 1] : z4;
        float4 hn = (tid < 511) ? row4[tid * 2 + 2] : z4;

        float w[16];
        w[0]=hp.x;  w[1]=hp.y;  w[2]=hp.z;  w[3]=hp.w;
        w[4]=c0.x;  w[5]=c0.y;  w[6]=c0.z;  w[7]=c0.w;
        w[8]=c1.x;  w[9]=c1.y;  w[10]=c1.z; w[11]=c1.w;
        w[12]=hn.x; w[13]=hn.y; w[14]=hn.z; w[15]=hn.w;

        #pragma unroll
        for (int t = 0; t < 9; t++) {
            float e = sE[m * 9 + t];
            #pragma unroll
            for (int jj = 0; jj < 8; jj++)
                u[jj] = fmaf(e, w[jj + t], u[jj]);
        }
    }

    // segment transform V -> A8*V + bacc
    float bacc = 0.f;
    #pragma unroll
    for (int jj = 0; jj < 8; jj++) bacc = fmaf(ALPHA, bacc, u[jj]);

    // warp-inclusive scan of (a,b) composition
    float a = A8, bs = bacc;
    #pragma unroll
    for (int s = 1; s < 32; s <<= 1) {
        float ao = __shfl_up_sync(0xffffffffu, a, s);
        float bo = __shfl_up_sync(0xffffffffu, bs, s);
        if (lane >= s) { bs = fmaf(a, bo, bs); a *= ao; }
    }
    if (lane == 31) { swa[wrp] = a; swb[wrp] = bs; }
    __syncthreads();

    float pb = 0.f;
    for (int ww = 0; ww < wrp; ww++) pb = fmaf(swa[ww], pb, swb[ww]);

    float ae  = __shfl_up_sync(0xffffffffu, a, 1);
    float bse = __shfl_up_sync(0xffffffffu, bs, 1);
    if (lane == 0) { ae = 1.f; bse = 0.f; }
    float V = fmaf(ae, pb, bse);   // V at start of this thread's segment

    int t0 = tid * 8;
    int ft = 0x7fffffff;
    #pragma unroll
    for (int jj = 0; jj < 8; jj++) {
        V = fmaf(ALPHA, V, u[jj]);
        if (V >= 1.0f && ft == 0x7fffffff) ft = t0 + jj;
    }
    if (ft != 0x7fffffff) atomicMin(&s_first, ft);
    __syncthreads();

    if (tid == 0) {
        float tl = (float)s_first;
        out[BC + bc] = tl;
        out[2 * BC + bc] = expf(-tl / s_scale);
    }
}

// ---------------- fused tail: act -> mix -> h -> pred. One block per batch row ----------------
__global__ void __launch_bounds__(256) k_tail(const float* __restrict__ OG,
                                              const float* __restrict__ bias,
                                              const float* __restrict__ W1,
                                              const float* __restrict__ b1,
                                              const float* __restrict__ W2,
                                              const float* __restrict__ b2,
                                              float* __restrict__ out) {
    __shared__ float4 sact4[64];
    __shared__ float smix[256];
    __shared__ float sh[128];
    __shared__ float sp[1024];

    int b = blockIdx.x;
    int t = threadIdx.x;
    int lane = t & 31;
    int wrp  = t >> 5;

    if (t < 64) sact4[t] = ((const float4*)(out + 2 * BC + b * CC))[t];
    __syncthreads();

    const float4* OG4 = (const float4*)OG;
    #pragma unroll 4
    for (int oo = 0; oo < 32; oo++) {
        int i = wrp * 32 + oo;
        float4 g0 = OG4[i * 64 + lane];
        float4 g1 = OG4[i * 64 + 32 + lane];
        float4 a0 = sact4[lane];
        float4 a1 = sact4[32 + lane];
        float acc = g0.x * a0.x;
        acc = fmaf(g0.y, a0.y, acc);
        acc = fmaf(g0.z, a0.z, acc);
        acc = fmaf(g0.w, a0.w, acc);
        acc = fmaf(g1.x, a1.x, acc);
        acc = fmaf(g1.y, a1.y, acc);
        acc = fmaf(g1.z, a1.z, acc);
        acc = fmaf(g1.w, a1.w, acc);
        #pragma unroll
        for (int s = 16; s > 0; s >>= 1) acc += __shfl_xor_sync(0xffffffffu, acc, s);
        if (lane == 0) smix[i] = acc + bias[i];
    }
    __syncthreads();

    {
        const float4* W14 = (const float4*)W1;
        int il = t & 31;
        int ch = t >> 5;
        float4 acc = make_float4(0.f, 0.f, 0.f, 0.f);
        #pragma unroll 8
        for (int jj = 0; jj < 32; jj++) {
            int j = ch * 32 + jj;
            float mj = smix[j];
            float4 wr = W14[j * 32 + il];
            acc.x = fmaf(mj, wr.x, acc.x);
            acc.y = fmaf(mj, wr.y, acc.y);
            acc.z = fmaf(mj, wr.z, acc.z);
            acc.w = fmaf(mj, wr.w, acc.w);
        }
        ((float4*)sp)[ch * 32 + il] = acc;
    }
    __syncthreads();
    if (t < 128) {
        float s = b1[t];
        #pragma unroll
        for (int ch = 0; ch < 8; ch++) s += sp[ch * 128 + t];
        sh[t] = fmaxf(s, 0.f);
    }
    __syncthreads();

    {
        const float4* W24 = (const float4*)W2;
        int il = t & 63;
        int ch = t >> 6;
        float4 acc = make_float4(0.f, 0.f, 0.f, 0.f);
        #pragma unroll 8
        for (int kk = 0; kk < 32; kk++) {
            int k = ch * 32 + kk;
            float hk = sh[k];
            float4 wr = W24[k * 64 + il];
            acc.x = fmaf(hk, wr.x, acc.x);
            acc.y = fmaf(hk, wr.y, acc.y);
            acc.z = fmaf(hk, wr.z, acc.z);
            acc.w = fmaf(hk, wr.w, acc.w);
        }
        ((float4*)sp)[ch * 64 + il] = acc;
    }
    __syncthreads();
    {
        float r = b2[t];
        #pragma unroll
        for (int ch = 0; ch < 4; ch++) r += sp[ch * 256 + t];
        float spv = (r > 20.f) ? r : log1pf(expf(r));
        out[b * CC + t] = fminf(spv, 4096.0f);
    }
}

extern "C" void kernel_launch(void* const* d_in, const int* in_sizes, int n_in,
                              void* d_out, int out_size) {
    const float* x    = (const float*)d_in[0];
    const float* w3   = (const float*)d_in[1];
    const float* b3   = (const float*)d_in[2];
    const float* w5   = (const float*)d_in[3];
    const float* b5   = (const float*)d_in[4];
    const float* w9   = (const float*)d_in[5];
    const float* b9   = (const float*)d_in[6];
    const float* wred = (const float*)d_in[7];
    const float* bred = (const float*)d_in[8];
    const float* ls   = (const float*)d_in[9];
    const float* og   = (const float*)d_in[10];
    const float* bias = (const float*)d_in[11];
    const float* W1   = (const float*)d_in[12];
    const float* b1   = (const float*)d_in[13];
    const float* W2   = (const float*)d_in[14];
    const float* b2   = (const float*)d_in[15];
    float* out = (float*)d_out;

    prep_kernel<<<24, 256>>>(w3, b3, w5, b5, w9, b9, wred, bred);
    prep_bias2<<<1, 256>>>(w3, b3, w5, b5, w9, b9, wred, bred);
    lif_kernel<<<BC, 512>>>(x, ls, out);
    k_tail<<<BB, 256>>>(og, bias, W1, b1, W2, b2, out);
}

// round 10
// speedup vs baseline: 1.8593x; 1.2065x over previous
#include <cuda_runtime.h>
#include <math.h>

#define CC 256
#define TT 4096
#define BB 8
#define BC (BB*CC)
#define ALPHA 0.8187307530779818f
#define ONE_M_ALPHA 0.1812692469220182f
#define A8 0.20189651799465540f   /* ALPHA^8 = exp(-1.6) */

// Effective-filter coefficients (scalar), already * (1-alpha)
__device__ float g_E[CC][3][9];
__device__ float g_beP[CC][3];     // bias partials * (1-alpha); m=0 slot includes bred

// ---------------- prep: 8 lanes per (c,m) pair; shfl-tree reduction ----------------
__global__ void __launch_bounds__(256) prep_kernel(
        const float* __restrict__ w3, const float* __restrict__ b3,
        const float* __restrict__ w5, const float* __restrict__ b5,
        const float* __restrict__ w9, const float* __restrict__ b9,
        const float* __restrict__ wred, const float* __restrict__ bred) {
    int tid = blockIdx.x * 256 + threadIdx.x;
    int pg  = tid >> 3;            // 0..767
    int sub = tid & 7;
    if (pg >= 3 * CC) return;
    int c = pg / 3;
    int m = pg - 3 * c;
    int j0 = 18 * c + 6 * m;
    const float* w; const float* bb; int K, pc0;
    if (j0 < 6 * CC)       { w = w3; bb = b3; K = 3; pc0 = j0; }
    else if (j0 < 12 * CC) { w = w5; bb = b5; K = 5; pc0 = j0 - 6 * CC; }
    else                   { w = w9; bb = b9; K = 9; pc0 = j0 - 12 * CC; }
    int pad = (K - 1) / 2;

    float E[9];
    #pragma unroll
    for (int t = 0; t < 9; t++) E[t] = 0.f;
    float be = 0.f;

    if (sub < 6) {
        int r = sub;
        float wr = wred[c * 18 + 6 * m + r];
        be = wr * bb[pc0 + r];
        for (int u = 0; u < K; u++)
            E[4 + u - pad] = wr * w[(pc0 + r) * K + u];
    }
    #pragma unroll
    for (int s = 4; s > 0; s >>= 1) {
        #pragma unroll
        for (int t = 0; t < 9; t++) E[t] += __shfl_xor_sync(0xffffffffu, E[t], s);
        be += __shfl_xor_sync(0xffffffffu, be, s);
    }
    if (sub == 0) {
        #pragma unroll
        for (int t = 0; t < 9; t++) g_E[c][m][t] = E[t] * ONE_M_ALPHA;
        g_beP[c][m] = be * ONE_M_ALPHA + ((m == 0) ? bred[c] * ONE_M_ALPHA : 0.f);
    }
}

// ---------------- lif: one block per (b, c); 512 threads, 8 timesteps/thread, SCALAR ----------------
// out layout: [0,BC) pred (by k_tail), [BC,2BC) true_latency, [2BC,3BC) act.
__global__ void __launch_bounds__(512, 3) lif_kernel(const float* __restrict__ x,
                                                     const float* __restrict__ lat_scale,
                                                     float* __restrict__ out) {
    __shared__ float sE[27];
    __shared__ float swa[16], swb[16];
    __shared__ float s_scale;
    __shared__ int s_first;

    int tid  = threadIdx.x;
    int lane = tid & 31;
    int wrp  = tid >> 5;
    int bc = blockIdx.x;
    int b  = bc >> 8;
    int c  = bc & 255;

    if (tid < 27) sE[tid] = ((const float*)g_E)[c * 27 + tid];
    if (tid == 28) s_first = TT;
    if (tid == 29) s_scale = fmaxf(lat_scale[0], 0.001f);
    __syncthreads();

    float u[8];
    float be = g_beP[c][0] + g_beP[c][1] + g_beP[c][2];
    #pragma unroll
    for (int jj = 0; jj < 8; jj++) u[jj] = be;

    const float4 z4 = make_float4(0.f, 0.f, 0.f, 0.f);
    #pragma unroll
    for (int m = 0; m < 3; m++) {
        int xch = (3 * c + m) & 255;
        const float4* row4 = (const float4*)(x + ((size_t)(b * CC + xch)) * TT);
        float4 c0 = row4[tid * 2 + 0];
        float4 c1 = row4[tid * 2 + 1];
        float4 hp = (tid > 0)   ? row4[tid * 2 - 1] : z4;
        float4 hn = (tid < 511) ? row4[tid * 2 + 2] : z4;

        float w[16];
        w[0]=hp.x;  w[1]=hp.y;  w[2]=hp.z;  w[3]=hp.w;
        w[4]=c0.x;  w[5]=c0.y;  w[6]=c0.z;  w[7]=c0.w;
        w[8]=c1.x;  w[9]=c1.y;  w[10]=c1.z; w[11]=c1.w;
        w[12]=hn.x; w[13]=hn.y; w[14]=hn.z; w[15]=hn.w;

        #pragma unroll
        for (int t = 0; t < 9; t++) {
            float e = sE[m * 9 + t];
            #pragma unroll
            for (int jj = 0; jj < 8; jj++)
                u[jj] = fmaf(e, w[jj + t], u[jj]);
        }
    }

    // segment transform V -> A8*V + bacc
    float bacc = 0.f;
    #pragma unroll
    for (int jj = 0; jj < 8; jj++) bacc = fmaf(ALPHA, bacc, u[jj]);

    // warp-inclusive scan of (a,b) composition
    float a = A8, bs = bacc;
    #pragma unroll
    for (int s = 1; s < 32; s <<= 1) {
        float ao = __shfl_up_sync(0xffffffffu, a, s);
        float bo = __shfl_up_sync(0xffffffffu, bs, s);
        if (lane >= s) { bs = fmaf(a, bo, bs); a *= ao; }
    }
    if (lane == 31) { swa[wrp] = a; swb[wrp] = bs; }
    __syncthreads();

    float pb = 0.f;
    for (int ww = 0; ww < wrp; ww++) pb = fmaf(swa[ww], pb, swb[ww]);

    float ae  = __shfl_up_sync(0xffffffffu, a, 1);
    float bse = __shfl_up_sync(0xffffffffu, bs, 1);
    if (lane == 0) { ae = 1.f; bse = 0.f; }
    float V = fmaf(ae, pb, bse);   // V at start of this thread's segment

    int t0 = tid * 8;
    int ft = 0x7fffffff;
    #pragma unroll
    for (int jj = 0; jj < 8; jj++) {
        V = fmaf(ALPHA, V, u[jj]);
        if (V >= 1.0f && ft == 0x7fffffff) ft = t0 + jj;
    }
    if (ft != 0x7fffffff) atomicMin(&s_first, ft);
    __syncthreads();

    if (tid == 0) {
        float tl = (float)s_first;
        out[BC + bc] = tl;
        out[2 * BC + bc] = expf(-tl / s_scale);
    }
}

// ---------------- fused tail: act -> mix -> h -> pred. 1024 threads per batch row ----------------
__global__ void __launch_bounds__(1024) k_tail(const float* __restrict__ OG,
                                               const float* __restrict__ bias,
                                               const float* __restrict__ W1,
                                               const float* __restrict__ b1,
                                               const float* __restrict__ W2,
                                               const float* __restrict__ b2,
                                               float* __restrict__ out) {
    __shared__ float4 sact4[64];
    __shared__ float smix[256];
    __shared__ float sh[128];
    __shared__ float sp[4096];      // 16KB: [32][128] for h, [16][256] for pred

    int b = blockIdx.x;
    int t = threadIdx.x;
    int lane = t & 31;
    int wrp  = t >> 5;              // 0..31

    if (t < 64) sact4[t] = ((const float4*)(out + 2 * BC + b * CC))[t];
    __syncthreads();

    // ---- mix: 32 warps x 8 outputs; 16 independent float4 loads per lane ----
    const float4* OG4 = (const float4*)OG;
    float4 a0 = sact4[lane];
    float4 a1 = sact4[32 + lane];
    #pragma unroll
    for (int oo = 0; oo < 8; oo++) {
        int i = wrp * 8 + oo;
        float4 g0 = OG4[i * 64 + lane];
        float4 g1 = OG4[i * 64 + 32 + lane];
        float acc = g0.x * a0.x;
        acc = fmaf(g0.y, a0.y, acc);
        acc = fmaf(g0.z, a0.z, acc);
        acc = fmaf(g0.w, a0.w, acc);
        acc = fmaf(g1.x, a1.x, acc);
        acc = fmaf(g1.y, a1.y, acc);
        acc = fmaf(g1.z, a1.z, acc);
        acc = fmaf(g1.w, a1.w, acc);
        #pragma unroll
        for (int s = 16; s > 0; s >>= 1) acc += __shfl_xor_sync(0xffffffffu, acc, s);
        if (lane == 0) smix[i] = acc + bias[i];
    }
    __syncthreads();

    // ---- h: 32 j-chunks of 8; thread -> 4 cols (il*4) ----
    {
        const float4* W14 = (const float4*)W1;
        int il = t & 31;
        int ch = t >> 5;
        float4 acc = make_float4(0.f, 0.f, 0.f, 0.f);
        #pragma unroll
        for (int jj = 0; jj < 8; jj++) {
            int j = ch * 8 + jj;
            float mj = smix[j];
            float4 wr = W14[j * 32 + il];
            acc.x = fmaf(mj, wr.x, acc.x);
            acc.y = fmaf(mj, wr.y, acc.y);
            acc.z = fmaf(mj, wr.z, acc.z);
            acc.w = fmaf(mj, wr.w, acc.w);
        }
        ((float4*)sp)[ch * 32 + il] = acc;
    }
    __syncthreads();
    if (t < 128) {
        float s = b1[t];
        #pragma unroll
        for (int ch = 0; ch < 32; ch++) s += sp[ch * 128 + t];
        sh[t] = fmaxf(s, 0.f);
    }
    __syncthreads();

    // ---- pred: 16 k-chunks of 8; thread -> 4 cols (il*4) ----
    {
        const float4* W24 = (const float4*)W2;
        int il = t & 63;
        int ch = t >> 6;
        float4 acc = make_float4(0.f, 0.f, 0.f, 0.f);
        #pragma unroll
        for (int kk = 0; kk < 8; kk++) {
            int k = ch * 8 + kk;
            float hk = sh[k];
            float4 wr = W24[k * 64 + il];
            acc.x = fmaf(hk, wr.x, acc.x);
            acc.y = fmaf(hk, wr.y, acc.y);
            acc.z = fmaf(hk, wr.z, acc.z);
            acc.w = fmaf(hk, wr.w, acc.w);
        }
        ((float4*)sp)[ch * 64 + il] = acc;
    }
    __syncthreads();
    if (t < 256) {
        float r = b2[t];
        #pragma unroll
        for (int ch = 0; ch < 16; ch++) r += sp[ch * 256 + t];
        float spv = (r > 20.f) ? r : log1pf(expf(r));
        out[b * CC + t] = fminf(spv, 4096.0f);
    }
}

extern "C" void kernel_launch(void* const* d_in, const int* in_sizes, int n_in,
                              void* d_out, int out_size) {
    const float* x    = (const float*)d_in[0];
    const float* w3   = (const float*)d_in[1];
    const float* b3   = (const float*)d_in[2];
    const float* w5   = (const float*)d_in[3];
    const float* b5   = (const float*)d_in[4];
    const float* w9   = (const float*)d_in[5];
    const float* b9   = (const float*)d_in[6];
    const float* wred = (const float*)d_in[7];
    const float* bred = (const float*)d_in[8];
    const float* ls   = (const float*)d_in[9];
    const float* og   = (const float*)d_in[10];
    const float* bias = (const float*)d_in[11];
    const float* W1   = (const float*)d_in[12];
    const float* b1   = (const float*)d_in[13];
    const float* W2   = (const float*)d_in[14];
    const float* b2   = (const float*)d_in[15];
    float* out = (float*)d_out;

    prep_kernel<<<24, 256>>>(w3, b3, w5, b5, w9, b9, wred, bred);
    lif_kernel<<<BC, 512>>>(x, ls, out);
    k_tail<<<BB, 1024>>>(og, bias, W1, b1, W2, b2, out);
}